// round 10
// baseline (speedup 1.0000x reference)
#include <cuda_runtime.h>

// Shapes: field/gt_field (8,4,64,128,64) f32, ct/gt_ct (8,1) f32, sdf (8,1,64,128,64) f32.
// Output: scalar f32 total loss. Single fused kernel, float4 along W, shfl x-edges,
// batched DRAM front (9 loads), interior merged into 2 windows of 8 loads (p+u, v+w).

#define NB 8
#define ND 64
#define NH 128
#define NW 64
#define SP (ND*NH*NW)
#define CS SP
#define NPTS (NB*SP)
#define NVEC (NPTS/4)          // 1048576 float4 quads
#define NBLK (NVEC/256)        // 4096 blocks

#define DXd ((2.0 + 0.5) / 63.0)
#define DYd ((0.5 + 0.5) / 127.0)
#define DZd ((0.3 + 0.5) / 63.0)

constexpr float c_inv2dx = (float)(1.0 / (2.0 * DXd));
constexpr float c_inv2dy = (float)(1.0 / (2.0 * DYd));
constexpr float c_inv2dz = (float)(1.0 / (2.0 * DZd));
constexpr float c_idx2   = (float)(1.0 / (DXd * DXd));
constexpr float c_idy2   = (float)(1.0 / (DYd * DYd));
constexpr float c_idz2   = (float)(1.0 / (DZd * DZd));

constexpr float c_sc_field  = (float)(1.0  / (double)(NB*4*SP));
constexpr float c_sc_ct     = (float)(10.0 / 8.0);
constexpr float c_sc_cm     = (float)(1.0  / (double)(NB*(ND-2)*(NH-2)*(NW-2)));
constexpr float c_sc_noslip = (float)(10.0 / (double)NPTS);
constexpr float c_sc_inlet  = (float)(5.0  / (double)(NB*ND*NH));
constexpr float c_sc_outlet = (float)(1.0  / (double)(NB*ND*NH));

#define INV_RE 1.0e-6f
#define OY NW
#define OZ (NH*NW)
#define FULLMASK 0xffffffffu

__device__ double g_acc = 0.0;
__device__ unsigned int g_count = 0;

__device__ __forceinline__ float4 ld4(const float* p) {
    return *reinterpret_cast<const float4*>(p);
}
__device__ __forceinline__ float4 ld4cs(const float* p) {
    return __ldcs(reinterpret_cast<const float4*>(p));
}

__global__ void __launch_bounds__(256, 4) k_loss(
    const float* __restrict__ field,
    const float* __restrict__ ct,
    const float* __restrict__ gt_field,
    const float* __restrict__ gt_ct,
    const float* __restrict__ sdf,
    float* __restrict__ out)
{
    const int vid = blockIdx.x * 256 + threadIdx.x;   // exactly NVEC threads
    const int wq = vid & 15;
    const int h  = (vid >> 4)  & (NH - 1);
    const int d  = (vid >> 11) & (ND - 1);
    const int b  = vid >> 17;

    const int sidx  = ((d * NH + h) << 6) + (wq << 2);
    const float* fb = field    + b * (4 * SP) + sidx;
    const float* gb = gt_field + b * (4 * SP) + sidx;

    float acc = 0.0f;

    if (vid < 8) {
        float dct = ct[vid] - gt_ct[vid];
        acc += c_sc_ct * dct * dct;
    }

    // ---- batched DRAM front loads: 9 LDG.128 issued back-to-back ----
    float4 cv[4], gv[4], svv;
    #pragma unroll
    for (int c = 0; c < 4; c++) cv[c] = ld4(fb + c * CS);
    #pragma unroll
    for (int c = 0; c < 4; c++) gv[c] = ld4cs(gb + c * CS);
    svv = ld4cs(sdf + b * SP + sidx);

    // velocity centers persist as scalars
    float Fv[3][4];
    #pragma unroll
    for (int c = 0; c < 3; c++) {
        Fv[c][0] = cv[c].x; Fv[c][1] = cv[c].y;
        Fv[c][2] = cv[c].z; Fv[c][3] = cv[c].w;
    }

    // field MSE, all 4 channels
    {
        float m = 0.0f;
        #pragma unroll
        for (int c = 0; c < 4; c++) {
            float d0 = cv[c].x - gv[c].x, d1 = cv[c].y - gv[c].y;
            float d2 = cv[c].z - gv[c].z, d3 = cv[c].w - gv[c].w;
            m += d0*d0 + d1*d1 + d2*d2 + d3*d3;
        }
        acc += c_sc_field * m;
    }

    float Sv[4] = {svv.x, svv.y, svv.z, svv.w};

    // no-slip (sdf <= 0)
    {
        float m = 0.0f;
        #pragma unroll
        for (int l = 0; l < 4; l++) {
            float q = Fv[0][l]*Fv[0][l] + Fv[1][l]*Fv[1][l] + Fv[2][l]*Fv[2][l];
            m += (Sv[l] <= 0.0f) ? q : 0.0f;
        }
        acc += c_sc_noslip * m;
    }

    // inlet / outlet
    if (wq == 0) {
        float du0 = Fv[0][0] - 1.0f;
        acc += c_sc_inlet * (du0*du0 + Fv[1][0]*Fv[1][0] + Fv[2][0]*Fv[2][0]);
    }
    if (wq == 15) {
        float a0 = Fv[0][3] - Fv[0][2];
        float a1 = Fv[1][3] - Fv[1][2];
        float a2 = Fv[2][3] - Fv[2][2];
        acc += c_sc_outlet * (a0*a0 + a1*a1 + a2*a2);
    }

    const bool yz_interior = (d >= 1) & (d <= ND - 2) & (h >= 1) & (h <= NH - 2);

    // ---- x-edge neighbors via warp shuffle (uniform, full warp) ----
    // Row-crossing lanes (wq==0/15) are zero-masked by wgt[] below.
    float Lcs[4], Rcs[4];
    #pragma unroll
    for (int c = 0; c < 3; c++) {
        Lcs[c] = __shfl_up_sync  (FULLMASK, Fv[c][3], 1);
        Rcs[c] = __shfl_down_sync(FULLMASK, Fv[c][0], 1);
    }
    Lcs[3] = __shfl_up_sync  (FULLMASK, cv[3].w, 1);
    Rcs[3] = __shfl_down_sync(FULLMASK, cv[3].x, 1);

    // ---- interior continuity + momentum: 2 load windows ----
    if (yz_interior) {
        float wgt[4];
        wgt[0] = (wq != 0  && Sv[0] > 0.0f) ? 1.0f : 0.0f;
        wgt[1] = (Sv[1] > 0.0f) ? 1.0f : 0.0f;
        wgt[2] = (Sv[2] > 0.0f) ? 1.0f : 0.0f;
        wgt[3] = (wq != 15 && Sv[3] > 0.0f) ? 1.0f : 0.0f;

        float msum = 0.0f;
        float gpy[4], gpz[4], divp[4];

        // ===== window 1: p + u neighbors (8 LDG.128 back-to-back) =====
        {
            const float* pb = fb + 3 * CS;
            float4 pyp = ld4(pb + OY), pym = ld4(pb - OY);
            float4 pzp = ld4(pb + OZ), pzm = ld4(pb - OZ);
            float4 uyp = ld4(fb + OY), uym = ld4(fb - OY);
            float4 uzp = ld4(fb + OZ), uzm = ld4(fb - OZ);

            gpy[0] = (pyp.x - pym.x) * c_inv2dy;
            gpy[1] = (pyp.y - pym.y) * c_inv2dy;
            gpy[2] = (pyp.z - pym.z) * c_inv2dy;
            gpy[3] = (pyp.w - pym.w) * c_inv2dy;
            gpz[0] = (pzp.x - pzm.x) * c_inv2dz;
            gpz[1] = (pzp.y - pzm.y) * c_inv2dz;
            gpz[2] = (pzp.z - pzm.z) * c_inv2dz;
            gpz[3] = (pzp.w - pzm.w) * c_inv2dz;

            float pctr[4] = {cv[3].x, cv[3].y, cv[3].z, cv[3].w};
            float uypA[4] = {uyp.x, uyp.y, uyp.z, uyp.w};
            float uymA[4] = {uym.x, uym.y, uym.z, uym.w};
            float uzpA[4] = {uzp.x, uzp.y, uzp.z, uzp.w};
            float uzmA[4] = {uzm.x, uzm.y, uzm.z, uzm.w};

            #pragma unroll
            for (int l = 0; l < 4; l++) {
                float u = Fv[0][l], v = Fv[1][l], w = Fv[2][l];
                float xm  = (l == 0) ? Lcs[0] : Fv[0][l - 1];
                float xp  = (l == 3) ? Rcs[0] : Fv[0][l + 1];
                float pxm = (l == 0) ? Lcs[3] : pctr[l - 1];
                float pxp = (l == 3) ? Rcs[3] : pctr[l + 1];

                float gxu  = (xp - xm) * c_inv2dx;
                float gpxl = (pxp - pxm) * c_inv2dx;
                float gyu  = (uypA[l] - uymA[l]) * c_inv2dy;
                float gzu  = (uzpA[l] - uzmA[l]) * c_inv2dz;
                float lapu = (xp + xm - 2.0f*u) * c_idx2
                           + (uypA[l] + uymA[l] - 2.0f*u) * c_idy2
                           + (uzpA[l] + uzmA[l] - 2.0f*u) * c_idz2;

                float rx = u*gxu + v*gyu + w*gzu + gpxl - INV_RE*lapu;
                msum += wgt[l] * rx * rx;
                divp[l] = gxu;
            }
        }

        // ===== window 2: v + w neighbors (8 LDG.128 back-to-back) =====
        {
            const float* vb = fb + CS;
            const float* wb = fb + 2 * CS;
            float4 vyp = ld4(vb + OY), vym = ld4(vb - OY);
            float4 vzp = ld4(vb + OZ), vzm = ld4(vb - OZ);
            float4 wyp = ld4(wb + OY), wym = ld4(wb - OY);
            float4 wzp = ld4(wb + OZ), wzm = ld4(wb - OZ);

            float vypA[4] = {vyp.x, vyp.y, vyp.z, vyp.w};
            float vymA[4] = {vym.x, vym.y, vym.z, vym.w};
            float vzpA[4] = {vzp.x, vzp.y, vzp.z, vzp.w};
            float vzmA[4] = {vzm.x, vzm.y, vzm.z, vzm.w};
            float wypA[4] = {wyp.x, wyp.y, wyp.z, wyp.w};
            float wymA[4] = {wym.x, wym.y, wym.z, wym.w};
            float wzpA[4] = {wzp.x, wzp.y, wzp.z, wzp.w};
            float wzmA[4] = {wzm.x, wzm.y, wzm.z, wzm.w};

            #pragma unroll
            for (int l = 0; l < 4; l++) {
                float u = Fv[0][l], v = Fv[1][l], w = Fv[2][l];

                float xmv = (l == 0) ? Lcs[1] : Fv[1][l - 1];
                float xpv = (l == 3) ? Rcs[1] : Fv[1][l + 1];
                float gxv = (xpv - xmv) * c_inv2dx;
                float gyv = (vypA[l] - vymA[l]) * c_inv2dy;
                float gzv = (vzpA[l] - vzmA[l]) * c_inv2dz;
                float lapv = (xpv + xmv - 2.0f*v) * c_idx2
                           + (vypA[l] + vymA[l] - 2.0f*v) * c_idy2
                           + (vzpA[l] + vzmA[l] - 2.0f*v) * c_idz2;
                float ry = u*gxv + v*gyv + w*gzv + gpy[l] - INV_RE*lapv;
                msum += wgt[l] * ry * ry;

                float xmw = (l == 0) ? Lcs[2] : Fv[2][l - 1];
                float xpw = (l == 3) ? Rcs[2] : Fv[2][l + 1];
                float gxw = (xpw - xmw) * c_inv2dx;
                float gyw = (wypA[l] - wymA[l]) * c_inv2dy;
                float gzw = (wzpA[l] - wzmA[l]) * c_inv2dz;
                float lapw = (xpw + xmw - 2.0f*w) * c_idx2
                           + (wypA[l] + wymA[l] - 2.0f*w) * c_idy2
                           + (wzpA[l] + wzmA[l] - 2.0f*w) * c_idz2;
                float rz = u*gxw + v*gyw + w*gzw + gpz[l] - INV_RE*lapw;
                msum += wgt[l] * rz * rz;

                float div = divp[l] + gyv + gzw;
                msum += wgt[l] * div * div;
            }
        }

        acc += c_sc_cm * msum;
    }

    // ---- reduction: warp shfl (f32) -> block (f64) -> global atomic ----
    #pragma unroll
    for (int o = 16; o > 0; o >>= 1)
        acc += __shfl_down_sync(FULLMASK, acc, o);

    __shared__ double warpsum[8];
    if ((threadIdx.x & 31) == 0)
        warpsum[threadIdx.x >> 5] = (double)acc;
    __syncthreads();

    if (threadIdx.x == 0) {
        double t = 0.0;
        #pragma unroll
        for (int i = 0; i < 8; i++) t += warpsum[i];
        atomicAdd(&g_acc, t);
        __threadfence();
        unsigned int ticket = atomicAdd(&g_count, 1u);
        if (ticket == (unsigned)(gridDim.x - 1)) {
            double tot = atomicAdd(&g_acc, 0.0);
            out[0] = (float)tot;
            g_acc = 0.0;       // reset for next graph replay
            g_count = 0u;
            __threadfence();
        }
    }
}

extern "C" void kernel_launch(void* const* d_in, const int* in_sizes, int n_in,
                              void* d_out, int out_size)
{
    const float* field    = (const float*)d_in[0];
    const float* ct       = (const float*)d_in[1];
    const float* gt_field = (const float*)d_in[2];
    const float* gt_ct    = (const float*)d_in[3];
    const float* sdf      = (const float*)d_in[4];

    k_loss<<<NBLK, 256>>>(field, ct, gt_field, gt_ct, sdf, (float*)d_out);
}